// round 4
// baseline (speedup 1.0000x reference)
#include <cuda_runtime.h>
#include <cstdint>

#define DIM 512
#define BATCH 32
#define M_TOTAL 131072            /* 64*64*32 */
#define MTILE 128
#define KC 32                      /* k per chunk: 128B row */
#define NCHUNK (DIM/KC)            /* 16 */
#define NTHREADS 128
#define A_WORDS (MTILE*KC)         /* 4096 words = 16KB, XOR-swizzled, no pad */
#define B_STRIDE 40                /* padded B rows: banks (8tg+g)%32 bijective */

/* B operand, tf32-RNE: g_scaled[k*32+b] = rna_tf32(L[k]*style[b][k])  (k-major) */
__device__ uint32_t g_scaled[DIM * BATCH];

__global__ void prep_kernel(const float* __restrict__ style, const float* __restrict__ L) {
    int i = blockIdx.x * blockDim.x + threadIdx.x;
    if (i < DIM * BATCH) {
        int k = i >> 5, b = i & 31;
        float v = L[k] * style[b * DIM + k];
        uint32_t bits;
        asm("cvt.rna.tf32.f32 %0, %1;" : "=r"(bits) : "f"(v));
        g_scaled[i] = bits;
    }
}

__device__ __forceinline__ uint32_t smem_u32(const void* p) {
    return (uint32_t)__cvta_generic_to_shared(p);
}
__device__ __forceinline__ void cp16(uint32_t dst, const void* src) {
    asm volatile("cp.async.cg.shared.global [%0], [%1], 16;" :: "r"(dst), "l"(src));
}
__device__ __forceinline__ void cp_commit() {
    asm volatile("cp.async.commit_group;" ::: "memory");
}
__device__ __forceinline__ void cp_wait1() {
    asm volatile("cp.async.wait_group 1;" ::: "memory");
}
__device__ __forceinline__ void mma_tf32(float* d, const uint32_t* a, const uint32_t* b) {
    asm volatile(
        "mma.sync.aligned.m16n8k8.row.col.f32.tf32.tf32.f32 "
        "{%0,%1,%2,%3}, {%4,%5,%6,%7}, {%8,%9}, {%0,%1,%2,%3};"
        : "+f"(d[0]), "+f"(d[1]), "+f"(d[2]), "+f"(d[3])
        : "r"(a[0]), "r"(a[1]), "r"(a[2]), "r"(a[3]), "r"(b[0]), "r"(b[1]));
}
/* A word index for logical (row, word w) under 16B-granule swizzle seg^=(row&7) */
__device__ __forceinline__ int aidx(int row, int seg_x, int w_lo) {
    return row * 32 + seg_x * 4 + w_lo;
}

__global__ void __launch_bounds__(NTHREADS, 5)
gemm_kernel(const float* __restrict__ U, const float* __restrict__ mu, float* __restrict__ out)
{
    __shared__ uint32_t sA[2][A_WORDS];            /* 2 x 16 KB, swizzled */
    __shared__ uint32_t sB[2][KC * B_STRIDE];      /* 2 x  5 KB, padded  */

    const int tid = threadIdx.x;
    const int wid = tid >> 5;
    const int lid = tid & 31;
    const int g   = lid >> 2;      /* groupID 0..7 */
    const int tg  = lid & 3;       /* thread-in-group 0..3 */
    const int mbase = blockIdx.x * MTILE;

    auto prefetch = [&](int c, int buf) {
        /* A: 128 rows x 128 B (k-contiguous); swizzled 16B-granule destinations */
        const float* ubase = U + (size_t)mbase * DIM + c * KC;
        uint32_t adst = smem_u32(&sA[buf][0]);
        #pragma unroll
        for (int j = 0; j < 8; ++j) {
            int id  = j * NTHREADS + tid;
            int row = id >> 3, seg = id & 7;
            cp16(adst + (uint32_t)(row * 128 + ((seg ^ (row & 7)) << 4)),
                 ubase + (size_t)row * DIM + seg * 4);
        }
        /* B: 32 k-rows x 128 B, padded stride */
        const uint32_t* bsrc = g_scaled + c * KC * BATCH;
        uint32_t bdst = smem_u32(&sB[buf][0]);
        #pragma unroll
        for (int j = 0; j < 2; ++j) {
            int id  = j * NTHREADS + tid;
            int row = id >> 3, seg = id & 7;
            cp16(bdst + (uint32_t)(row * (B_STRIDE * 4) + seg * 16),
                 bsrc + (size_t)row * BATCH + seg * 4);
        }
    };

    float acc[2][4][4];
    #pragma unroll
    for (int mt = 0; mt < 2; ++mt)
        #pragma unroll
        for (int nt = 0; nt < 4; ++nt)
            #pragma unroll
            for (int r = 0; r < 4; ++r) acc[mt][nt][r] = 0.0f;

    prefetch(0, 0); cp_commit();
    prefetch(1, 1); cp_commit();

    for (int c = 0; c < NCHUNK; ++c) {
        cp_wait1();
        __syncthreads();
        const uint32_t* A = sA[c & 1];
        const uint32_t* B = sB[c & 1];

        #pragma unroll
        for (int ks = 0; ks < 4; ++ks) {
            uint32_t a[2][4], b[4][2];
            #pragma unroll
            for (int mt = 0; mt < 2; ++mt) {
                int r0 = wid * 32 + mt * 16 + g;      /* r0 & 7 == g */
                int r1 = r0 + 8;                       /* r1 & 7 == g */
                int s0 = (ks * 2) ^ g;                 /* seg of w=ks*8+tg   */
                int s1 = (ks * 2 + 1) ^ g;             /* seg of w=ks*8+tg+4 */
                /* +0x1000: RNE into tf32 (HW truncates low 13 bits) */
                a[mt][0] = A[aidx(r0, s0, tg)] + 0x1000u;
                a[mt][1] = A[aidx(r1, s0, tg)] + 0x1000u;
                a[mt][2] = A[aidx(r0, s1, tg)] + 0x1000u;
                a[mt][3] = A[aidx(r1, s1, tg)] + 0x1000u;
            }
            #pragma unroll
            for (int nt = 0; nt < 4; ++nt) {
                b[nt][0] = B[(ks * 8 + tg)     * B_STRIDE + nt * 8 + g];
                b[nt][1] = B[(ks * 8 + tg + 4) * B_STRIDE + nt * 8 + g];
            }
            #pragma unroll
            for (int mt = 0; mt < 2; ++mt)
                #pragma unroll
                for (int nt = 0; nt < 4; ++nt)
                    mma_tf32(acc[mt][nt], a[mt], b[nt]);
        }

        __syncthreads();
        if (c + 2 < NCHUNK) prefetch(c + 2, c & 1);
        cp_commit();   /* possibly-empty group keeps wait_group accounting simple */
    }

    /* epilogue: D[g][2tg..], add mu, store out[b][m] */
    #pragma unroll
    for (int mt = 0; mt < 2; ++mt) {
        int m0 = mbase + wid * 32 + mt * 16 + g;
        float mu0 = __ldg(&mu[m0]);
        float mu1 = __ldg(&mu[m0 + 8]);
        #pragma unroll
        for (int nt = 0; nt < 4; ++nt) {
            int b0 = nt * 8 + 2 * tg;
            out[(size_t)b0       * M_TOTAL + m0]     = acc[mt][nt][0] + mu0;
            out[(size_t)(b0 + 1) * M_TOTAL + m0]     = acc[mt][nt][1] + mu0;
            out[(size_t)b0       * M_TOTAL + m0 + 8] = acc[mt][nt][2] + mu1;
            out[(size_t)(b0 + 1) * M_TOTAL + m0 + 8] = acc[mt][nt][3] + mu1;
        }
    }
}

extern "C" void kernel_launch(void* const* d_in, const int* in_sizes, int n_in,
                              void* d_out, int out_size) {
    const float *style = nullptr, *U = nullptr, *L = nullptr, *mu = nullptr;
    for (int i = 0; i < n_in; ++i) {
        switch (in_sizes[i]) {
            case BATCH * DIM:   style = (const float*)d_in[i]; break;
            case M_TOTAL * DIM: U     = (const float*)d_in[i]; break;
            case DIM:           L     = (const float*)d_in[i]; break;
            case M_TOTAL:       mu    = (const float*)d_in[i]; break;
            default: break;
        }
    }
    float* out = (float*)d_out;

    prep_kernel<<<(BATCH * DIM + 255) / 256, 256>>>(style, L);
    gemm_kernel<<<M_TOTAL / MTILE, NTHREADS>>>(U, mu, out);
}

// round 5
// speedup vs baseline: 1.0011x; 1.0011x over previous
#include <cuda_runtime.h>
#include <cstdint>

#define DIM 512
#define BATCH 32
#define M_TOTAL 131072            /* 64*64*32 */
#define MTILE 128
#define KC 32                      /* k per chunk */
#define NCHUNK (DIM/KC)            /* 16 */
#define NTHREADS 128
#define B_WORDS (DIM*BATCH)        /* 16384 words = 64KB, fragment-ordered, resident */
#define AWARP_WORDS (32*KC)        /* 1024 words = 4KB per warp-chunk */
#define ASTAGES 3
#define SMEM_WORDS (B_WORDS + 4*ASTAGES*AWARP_WORDS)   /* 28672 words = 112KB */

/* B in per-lane MMA fragment order:
   g_bfrag[((c*4+ks)*2+h)*128 + lid*4 + nt] = rna_tf32(L[k]*style[b][k])
   with k = c*32+ks*8+(lid&3)+4h, b = nt*8+(lid>>2). */
__device__ uint32_t g_bfrag[B_WORDS];

__global__ void prep_kernel(const float* __restrict__ style, const float* __restrict__ L) {
    int i = blockIdx.x * blockDim.x + threadIdx.x;
    if (i < B_WORDS) {
        int nt  = i & 3;
        int lid = (i >> 2) & 31;
        int h   = (i >> 7) & 1;
        int ks  = (i >> 8) & 3;
        int c   = i >> 10;
        int k = c * 32 + ks * 8 + (lid & 3) + h * 4;
        int b = nt * 8 + (lid >> 2);
        float v = L[k] * style[b * DIM + k];
        uint32_t bits;
        asm("cvt.rna.tf32.f32 %0, %1;" : "=r"(bits) : "f"(v));
        g_bfrag[i] = bits;
    }
}

__device__ __forceinline__ uint32_t smem_u32(const void* p) {
    return (uint32_t)__cvta_generic_to_shared(p);
}
__device__ __forceinline__ void cp16(uint32_t dst, const void* src) {
    asm volatile("cp.async.cg.shared.global [%0], [%1], 16;" :: "r"(dst), "l"(src));
}
__device__ __forceinline__ void cp_commit() {
    asm volatile("cp.async.commit_group;" ::: "memory");
}
__device__ __forceinline__ void cp_wait2() {
    asm volatile("cp.async.wait_group 2;" ::: "memory");
}
__device__ __forceinline__ void mma_tf32(float* d, const uint32_t* a, uint32_t b0, uint32_t b1) {
    asm volatile(
        "mma.sync.aligned.m16n8k8.row.col.f32.tf32.tf32.f32 "
        "{%0,%1,%2,%3}, {%4,%5,%6,%7}, {%8,%9}, {%0,%1,%2,%3};"
        : "+f"(d[0]), "+f"(d[1]), "+f"(d[2]), "+f"(d[3])
        : "r"(a[0]), "r"(a[1]), "r"(a[2]), "r"(a[3]), "r"(b0), "r"(b1));
}

__global__ void __launch_bounds__(NTHREADS)
gemm_kernel(const float* __restrict__ U, const float* __restrict__ mu, float* __restrict__ out)
{
    extern __shared__ uint32_t smem[];     /* [0,16384): B  | then per-warp A rings */

    const int tid = threadIdx.x;
    const int wid = tid >> 5;
    const int lid = tid & 31;
    const int g   = lid >> 2;
    const int tg  = lid & 3;
    const int mbase = blockIdx.x * MTILE;

    uint32_t* const sA = &smem[B_WORDS + wid * ASTAGES * AWARP_WORDS];

    /* per-warp A prefetch: own 32 rows, chunk c, stage s; 16B-granule XOR swizzle */
    auto prefetchA = [&](int c, int s) {
        const float* ubase = U + (size_t)(mbase + wid * 32) * DIM + c * KC;
        uint32_t adst = smem_u32(&sA[s * AWARP_WORDS]);
        #pragma unroll
        for (int j = 0; j < 8; ++j) {
            int id  = j * 32 + lid;
            int row = id >> 3, seg = id & 7;
            cp16(adst + (uint32_t)(row * 128 + ((seg ^ (row & 7)) << 4)),
                 ubase + (size_t)row * DIM + seg * 4);
        }
    };

    /* one-time cooperative B load (group 0, shared with A chunk 0) */
    {
        uint32_t bdst = smem_u32(&smem[0]);
        const uint32_t* bsrc = g_bfrag;
        #pragma unroll
        for (int j = 0; j < 32; ++j) {
            int seg = j * NTHREADS + tid;
            cp16(bdst + (uint32_t)(seg * 16), bsrc + (size_t)seg * 4);
        }
    }
    prefetchA(0, 0); cp_commit();
    prefetchA(1, 1); cp_commit();
    prefetchA(2, 2); cp_commit();
    cp_wait2();
    __syncthreads();     /* B visible to all warps; the ONLY block barrier */

    float acc[2][4][4];
    #pragma unroll
    for (int mt = 0; mt < 2; ++mt)
        #pragma unroll
        for (int nt = 0; nt < 4; ++nt)
            #pragma unroll
            for (int r = 0; r < 4; ++r) acc[mt][nt][r] = 0.0f;

    int stage = 0;
    for (int c = 0; c < NCHUNK; ++c) {
        cp_wait2();      /* own groups: chunk c resident for this warp */
        const uint32_t* A = &sA[stage * AWARP_WORDS];

        #pragma unroll
        for (int ks = 0; ks < 4; ++ks) {
            /* B fragments: conflict-free LDS.128, broadcast-identical across warps */
            const uint4 p0 = *(const uint4*)&smem[((c * 4 + ks) * 2    ) * 128 + lid * 4];
            const uint4 p1 = *(const uint4*)&smem[((c * 4 + ks) * 2 + 1) * 128 + lid * 4];

            uint32_t a[2][4];
            #pragma unroll
            for (int mt = 0; mt < 2; ++mt) {
                int r0 = mt * 16 + g;          /* rows within this warp's subtile */
                int r1 = r0 + 8;               /* r&7 == g for both */
                int s0 = ((ks * 2)     ^ g) << 2;
                int s1 = ((ks * 2 + 1) ^ g) << 2;
                /* +0x1000: RNE into tf32 (HW truncates low 13 bits) */
                a[mt][0] = A[r0 * 32 + s0 + tg] + 0x1000u;
                a[mt][1] = A[r1 * 32 + s0 + tg] + 0x1000u;
                a[mt][2] = A[r0 * 32 + s1 + tg] + 0x1000u;
                a[mt][3] = A[r1 * 32 + s1 + tg] + 0x1000u;
            }
            #pragma unroll
            for (int mt = 0; mt < 2; ++mt) {
                mma_tf32(acc[mt][0], a[mt], p0.x, p1.x);
                mma_tf32(acc[mt][1], a[mt], p0.y, p1.y);
                mma_tf32(acc[mt][2], a[mt], p0.z, p1.z);
                mma_tf32(acc[mt][3], a[mt], p0.w, p1.w);
            }
        }

        if (c + 3 < NCHUNK) prefetchA(c + 3, stage);
        cp_commit();     /* possibly-empty group keeps per-thread wait accounting uniform */
        stage = (stage == 2) ? 0 : stage + 1;
    }

    /* epilogue: add mu, store out[b][m] (32B-coalesced per b-group) */
    #pragma unroll
    for (int mt = 0; mt < 2; ++mt) {
        int m0 = mbase + wid * 32 + mt * 16 + g;
        float mu0 = __ldg(&mu[m0]);
        float mu1 = __ldg(&mu[m0 + 8]);
        #pragma unroll
        for (int nt = 0; nt < 4; ++nt) {
            int b0 = nt * 8 + 2 * tg;
            out[(size_t)b0       * M_TOTAL + m0]     = acc[mt][nt][0] + mu0;
            out[(size_t)(b0 + 1) * M_TOTAL + m0]     = acc[mt][nt][1] + mu0;
            out[(size_t)b0       * M_TOTAL + m0 + 8] = acc[mt][nt][2] + mu1;
            out[(size_t)(b0 + 1) * M_TOTAL + m0 + 8] = acc[mt][nt][3] + mu1;
        }
    }
}

extern "C" void kernel_launch(void* const* d_in, const int* in_sizes, int n_in,
                              void* d_out, int out_size) {
    const float *style = nullptr, *U = nullptr, *L = nullptr, *mu = nullptr;
    for (int i = 0; i < n_in; ++i) {
        switch (in_sizes[i]) {
            case BATCH * DIM:   style = (const float*)d_in[i]; break;
            case M_TOTAL * DIM: U     = (const float*)d_in[i]; break;
            case DIM:           L     = (const float*)d_in[i]; break;
            case M_TOTAL:       mu    = (const float*)d_in[i]; break;
            default: break;
        }
    }
    float* out = (float*)d_out;

    cudaFuncSetAttribute(gemm_kernel, cudaFuncAttributeMaxDynamicSharedMemorySize,
                         SMEM_WORDS * 4);

    prep_kernel<<<(B_WORDS + 255) / 256, 256>>>(style, L);
    gemm_kernel<<<M_TOTAL / MTILE, NTHREADS, SMEM_WORDS * 4>>>(U, mu, out);
}